// round 5
// baseline (speedup 1.0000x reference)
#include <cuda_runtime.h>
#include <cuda_bf16.h>
#include <stdint.h>

#define BB 4096
#define DD 1024
#define RR 256
#define NCTA 128
#define NTHR 256

#define K_W1 1.3512071919596578
#define K_W0 (-1.7024143839193153)
#define K_C1f ((float)(K_W1 * 0.5))
#define K_C2f ((float)((K_W0 + K_W1) * 0.5))
#define K_DT 0.01f

// -------- device-global scratch (no runtime allocation) --------
__device__ __align__(1024) unsigned char g_Ub[16 * 32768];   // U bf16: 16 k-chunks [256n x 64k] SW128
__device__ __align__(1024) unsigned char g_Wb[64 * 8192];    // W bf16: 16 n-chunks x 4 k-tiles [64n x 64k] SW128
__device__ __align__(1024) float g_vf[(size_t)BB * DD];      // v fp32 master

// -------- helpers --------
__device__ __forceinline__ uint32_t swz(uint32_t o) { return o ^ ((o >> 3) & 0x70); }
__device__ __forceinline__ uint32_t s2u(const void* p) {
    uint32_t a; asm("{ .reg .u64 t; cvta.to.shared.u64 t, %1; cvt.u32.u64 %0, t; }" : "=r"(a) : "l"(p)); return a;
}
__device__ __forceinline__ uint32_t bf2u(__nv_bfloat162 b) { return *reinterpret_cast<uint32_t*>(&b); }
__device__ __forceinline__ void mb_init(uint32_t a, uint32_t c) {
    asm volatile("mbarrier.init.shared.b64 [%0], %1;" :: "r"(a), "r"(c) : "memory");
}
__device__ __forceinline__ void mb_expect(uint32_t a, uint32_t b) {
    asm volatile("mbarrier.arrive.expect_tx.shared.b64 _, [%0], %1;" :: "r"(a), "r"(b) : "memory");
}
__device__ __forceinline__ void mb_wait(uint32_t a, uint32_t p) {
    asm volatile("{\n\t.reg .pred P;\n\tLW%=:\n\t"
        "mbarrier.try_wait.parity.acquire.cta.shared::cta.b64 P, [%0], %1, 0x989680;\n\t"
        "@P bra LD%=;\n\tbra LW%=;\n\tLD%=:\n\t}" :: "r"(a), "r"(p) : "memory");
}
__device__ __forceinline__ void bulkcp(uint32_t d, const void* s, uint32_t n, uint32_t mb) {
    asm volatile("cp.async.bulk.shared::cluster.global.mbarrier::complete_tx::bytes [%0], [%1], %2, [%3];"
                 :: "r"(d), "l"(s), "r"(n), "r"(mb) : "memory");
}
__device__ __forceinline__ void fence_async_sh() { asm volatile("fence.proxy.async.shared::cta;" ::: "memory"); }
__device__ __forceinline__ void ldsm4(uint32_t* r, uint32_t a) {
    asm volatile("ldmatrix.sync.aligned.m8n8.x4.shared.b16 {%0,%1,%2,%3}, [%4];"
                 : "=r"(r[0]), "=r"(r[1]), "=r"(r[2]), "=r"(r[3]) : "r"(a));
}
__device__ __forceinline__ void mma16816(float* c, const uint32_t* a, const uint32_t* b) {
    asm volatile("mma.sync.aligned.m16n8k16.row.col.f32.bf16.bf16.f32 "
        "{%0,%1,%2,%3}, {%4,%5,%6,%7}, {%8,%9}, {%0,%1,%2,%3};"
        : "+f"(c[0]), "+f"(c[1]), "+f"(c[2]), "+f"(c[3])
        : "r"(a[0]), "r"(a[1]), "r"(a[2]), "r"(a[3]), "r"(b[0]), "r"(b[1]));
}
__device__ __forceinline__ void sts32(uint32_t a, uint32_t v) {
    asm volatile("st.shared.b32 [%0], %1;" :: "r"(a), "r"(v) : "memory");
}
__device__ __forceinline__ void sts64(uint32_t a, uint32_t v0, uint32_t v1) {
    asm volatile("st.shared.v2.u32 [%0], {%1, %2};" :: "r"(a), "r"(v0), "r"(v1) : "memory");
}
__device__ __forceinline__ const unsigned char* chunk_src(int g) {
    int l = g & 31;
    return (l < 16) ? (g_Ub + (size_t)l * 32768) : (g_Wb + (size_t)(l - 16) * 32768);
}

// -------- prologue: fp32 -> bf16 SW128 tiles in gmem --------
__global__ void prep_uw_kernel(const float* __restrict__ U, const float* __restrict__ W) {
    int idx = blockIdx.x * blockDim.x + threadIdx.x;       // 262144
    if (idx < 131072) {                                    // U: kc(16) x r(256) x j(32 pairs)
        int kc = idx >> 13, rem = idx & 8191, r = rem >> 5, j = rem & 31;
        float2 f = *(const float2*)(U + (size_t)r * DD + kc * 64 + j * 2);
        *(uint32_t*)(g_Ub + kc * 32768 + swz((uint32_t)(r * 128 + j * 4))) = bf2u(__float22bfloat162_rn(f));
    } else {                                               // W: 64 tiles (nc*4+kt) x dr(64) x j(32)
        int i2 = idx - 131072;
        int t = i2 >> 11, rem = i2 & 2047, dr = rem >> 5, j = rem & 31;
        int nc = t >> 2, kt = t & 3;
        float2 f = *(const float2*)(W + (size_t)(nc * 64 + dr) * RR + kt * 64 + j * 2);
        *(uint32_t*)(g_Wb + t * 8192 + swz((uint32_t)(dr * 128 + j * 4))) = bf2u(__float22bfloat162_rn(f));
    }
}

// -------- fused elementwise for one 64-d chunk --------
__device__ __forceinline__ void ew_chunk(
    int c, const float* SGb, int step, float dcoef,
    const float* __restrict__ x, const float* __restrict__ vsrc,
    const float* __restrict__ force, float* __restrict__ out,
    uint32_t SV, int er, int el, size_t grow)
{
    const float* SGrow = SGb + er * 68;
    #pragma unroll
    for (int i = 0; i < 2; ++i) {
        const int dl = el + i * 32;
        const int d = c * 64 + dl;
        float4 g4 = *(const float4*)(SGrow + dl);
        float4 f4 = *(const float4*)(force + grow + d);
        float4 v4 = *(const float4*)(vsrc + grow + d);
        float4 vn;
        vn.x = v4.x + dcoef * (f4.x - g4.x);
        vn.y = v4.y + dcoef * (f4.y - g4.y);
        vn.z = v4.z + dcoef * (f4.z - g4.z);
        vn.w = v4.w + dcoef * (f4.w - g4.w);
        *(float4*)(g_vf + grow + d) = vn;
        sts64(SV + (uint32_t)c * 4096u + swz((uint32_t)(er * 128 + dl * 2)),
              bf2u(__float22bfloat162_rn(make_float2(vn.x, vn.y))),
              bf2u(__float22bfloat162_rn(make_float2(vn.z, vn.w))));
        float4* ox = (float4*)(out + grow + d);
        if (step == 0) {
            float4 t;
            t.x = K_C1f * v4.x + K_C2f * vn.x; t.y = K_C1f * v4.y + K_C2f * vn.y;
            t.z = K_C1f * v4.z + K_C2f * vn.z; t.w = K_C1f * v4.w + K_C2f * vn.w;
            *ox = t;
        } else if (step == 1) {
            float4 t = *ox;
            t.x += K_C2f * vn.x; t.y += K_C2f * vn.y;
            t.z += K_C2f * vn.z; t.w += K_C2f * vn.w;
            *ox = t;
        } else {
            float4 t = *ox;
            float4 x4 = *(const float4*)(x + grow + d);
            t.x = x4.x + K_DT * (t.x + K_C1f * vn.x);
            t.y = x4.y + K_DT * (t.y + K_C1f * vn.y);
            t.z = x4.z + K_DT * (t.z + K_C1f * vn.z);
            t.w = x4.w + K_DT * (t.w + K_C1f * vn.w);
            *ox = t;
            *(float4*)(out + (size_t)BB * DD + grow + d) = vn;
        }
    }
}

// -------- main fused integrator --------
__global__ __launch_bounds__(NTHR, 1)
void yoshida_mma2_kernel(const float* __restrict__ x, const float* __restrict__ v,
                         const float* __restrict__ force, float* __restrict__ out) {
    extern __shared__ unsigned char dsm[];
    unsigned char* basep = (unsigned char*)(((uintptr_t)dsm + 1023u) & ~(uintptr_t)1023u);
    const uint32_t base = s2u(basep);
    const uint32_t SV   = base;                 // 64KB resident v bf16: 16 tiles [32 x 64] SW128
    const uint32_t RING = base + 65536u;        // 4 x 32KB unified U/W chunk ring
    const uint32_t H2   = base + 196608u;       // 4 x 4KB h^2 tiles [32 x 64] bf16 SW128
    float* SG0 = (float*)(basep + 212992u);     // sGamma ping [32][68] f32
    float* SG1 = (float*)(basep + 212992u + 8704u);
    const uint32_t BARS = base + 230400u;

    const int tid = threadIdx.x, wid = tid >> 5, lid = tid & 31;
    const int mh = wid >> 2;                   // M half: rows mh*16..+15
    const int q  = wid & 3;                    // N quadrant
    const int row0 = blockIdx.x * 32;

    const uint32_t arow = (uint32_t)((mh * 16 + (lid & 15)) * 128 + ((lid >> 4) << 4));
    const uint32_t brow = (uint32_t)(((lid & 7) + ((lid >> 4) << 3)) * 128 + (((lid >> 3) & 1) << 4));
    const int hr = lid >> 2, hc2 = (lid & 3) * 2;
    const int er = tid >> 3, el = (tid & 7) * 4;
    const size_t grow = (size_t)(row0 + er) * DD;

    if (tid == 0) {
        #pragma unroll
        for (int i = 0; i < 4; ++i) mb_init(BARS + 8u * i, 1);
        fence_async_sh();
        #pragma unroll
        for (int c = 0; c < 4; ++c) {          // prime the ring: chunks 0..3 (= U chunks 0..3)
            mb_expect(BARS + 8u * c, 32768u);
            bulkcp(RING + (uint32_t)c * 32768u, chunk_src(c), 32768u, BARS + 8u * c);
        }
    }

    // resident sV init: bf16(v) pre-swizzled (overlaps ring prefetch)
    for (int i = tid; i < 8192; i += NTHR) {
        int row = i >> 8, rem = i & 255, kc = rem >> 4, jj = rem & 15;
        float4 f = *(const float4*)(v + (size_t)(row0 + row) * DD + kc * 64 + jj * 4);
        sts64(SV + (uint32_t)kc * 4096u + swz((uint32_t)(row * 128 + jj * 8)),
              bf2u(__float22bfloat162_rn(make_float2(f.x, f.y))),
              bf2u(__float22bfloat162_rn(make_float2(f.z, f.w))));
    }
    __syncthreads();

    const float dctab[3] = { (float)K_W1 * K_DT, (float)K_W0 * K_DT, (float)K_W1 * K_DT };

    for (int step = 0; step < 3; ++step) {
        const float dcoef = dctab[step];
        const float* vsrc = (step == 0) ? v : g_vf;

        // ===== GEMM1: h[32 x 256] = sV @ U^T, K=1024 in 16 ring chunks =====
        float acc1[8][4];
        #pragma unroll
        for (int t = 0; t < 8; ++t)
            #pragma unroll
            for (int j = 0; j < 4; ++j) acc1[t][j] = 0.f;

        for (int kc = 0; kc < 16; ++kc) {
            const int b = kc & 3;
            mb_wait(BARS + 8u * b, (uint32_t)((kc >> 2) & 1));
            const uint32_t Ab = SV + (uint32_t)kc * 4096u;
            const uint32_t Bb = RING + (uint32_t)b * 32768u;
            #pragma unroll
            for (int ks = 0; ks < 4; ++ks) {
                uint32_t a[4];
                ldsm4(a, Ab + swz(arow + ks * 32));
                #pragma unroll
                for (int ntp = 0; ntp < 4; ++ntp) {
                    uint32_t bb[4];
                    ldsm4(bb, Bb + swz(brow + (uint32_t)((q * 64 + ntp * 16) * 128) + ks * 32));
                    mma16816(acc1[2 * ntp],     a, bb);
                    mma16816(acc1[2 * ntp + 1], a, bb + 2);
                }
            }
            __syncthreads();                   // all warps done with ring buf b
            const int g = step * 32 + kc;
            if (tid == 0 && g + 4 < 96) {
                mb_expect(BARS + 8u * b, 32768u);
                bulkcp(RING + (uint32_t)b * 32768u, chunk_src(g + 4), 32768u, BARS + 8u * b);
            }
        }

        // ---- h^2 -> bf16 SW128 H2 tiles ----
        {
            const uint32_t ht = H2 + (uint32_t)q * 4096u;
            #pragma unroll
            for (int nt = 0; nt < 8; ++nt) {
                float c0 = acc1[nt][0], c1 = acc1[nt][1], c2 = acc1[nt][2], c3 = acc1[nt][3];
                uint32_t p0 = bf2u(__float22bfloat162_rn(make_float2(c0 * c0, c1 * c1)));
                uint32_t p1 = bf2u(__float22bfloat162_rn(make_float2(c2 * c2, c3 * c3)));
                uint32_t koff = (uint32_t)((nt * 8 + hc2) * 2);
                sts32(ht + swz((uint32_t)((mh * 16 + hr) * 128) + koff), p0);
                sts32(ht + swz((uint32_t)((mh * 16 + hr + 8) * 128) + koff), p1);
            }
        }
        __syncthreads();

        // ===== GEMM2: Gamma = h2 @ W^T, 16 n-chunks of 64, software-pipelined =====
        float acc2[2][2][4];
        for (int it = 0; it <= 16; ++it) {
            if (it < 16) {
                const int b = it & 3;
                mb_wait(BARS + 8u * b, (uint32_t)((it >> 2) & 1));
                const int cur = it & 1;
                #pragma unroll
                for (int t = 0; t < 2; ++t)
                    #pragma unroll
                    for (int j = 0; j < 4; ++j) acc2[cur][t][j] = 0.f;
                const uint32_t Bc = RING + (uint32_t)b * 32768u;
                #pragma unroll
                for (int kt = 0; kt < 4; ++kt) {
                    const uint32_t At = H2 + (uint32_t)kt * 4096u;
                    const uint32_t Bt = Bc + (uint32_t)kt * 8192u;
                    #pragma unroll
                    for (int ks = 0; ks < 4; ++ks) {
                        uint32_t a[4], bb[4];
                        ldsm4(a,  At + swz(arow + ks * 32));
                        ldsm4(bb, Bt + swz(brow + (uint32_t)(q * 2048) + ks * 32));
                        mma16816(acc2[cur][0], a, bb);
                        mma16816(acc2[cur][1], a, bb + 2);
                    }
                }
            }
            if (it > 0) {   // SG store for previous chunk (pong accumulators)
                const int c = it - 1, pb = c & 1;
                float* SGb = pb ? SG1 : SG0;
                float (*A)[4] = acc2[pb];
                const int rbase = (mh * 16 + hr) * 68 + q * 16 + hc2;
                *(float2*)(SGb + rbase)           = make_float2(A[0][0], A[0][1]);
                *(float2*)(SGb + rbase + 8 * 68)  = make_float2(A[0][2], A[0][3]);
                *(float2*)(SGb + rbase + 8)       = make_float2(A[1][0], A[1][1]);
                *(float2*)(SGb + rbase + 8 * 68 + 8) = make_float2(A[1][2], A[1][3]);
            }
            __syncthreads();
            if (it < 16 && tid == 0) {
                const int g = step * 32 + 16 + it;
                if (g + 4 < 96) {
                    const int b = it & 3;
                    mb_expect(BARS + 8u * b, 32768u);
                    bulkcp(RING + (uint32_t)b * 32768u, chunk_src(g + 4), 32768u, BARS + 8u * b);
                }
            }
            if (it > 0) {   // elementwise for previous chunk (overlaps MMA of current)
                const int c = it - 1;
                ew_chunk(c, (c & 1) ? SG1 : SG0, step, dcoef, x, vsrc, force, out,
                         SV, er, el, grow);
            }
        }
    }
}

extern "C" void kernel_launch(void* const* d_in, const int* in_sizes, int n_in,
                              void* d_out, int out_size)
{
    const float* x     = (const float*)d_in[0];
    const float* v     = (const float*)d_in[1];
    const float* force = (const float*)d_in[2];
    const float* U     = (const float*)d_in[3];
    const float* W     = (const float*)d_in[4];
    float* out = (float*)d_out;

    const int smem_bytes = 231456;
    cudaFuncSetAttribute(yoshida_mma2_kernel, cudaFuncAttributeMaxDynamicSharedMemorySize, smem_bytes);

    prep_uw_kernel<<<1024, 256>>>(U, W);
    yoshida_mma2_kernel<<<NCTA, NTHR, smem_bytes>>>(x, v, force, out);
}

// round 6
// speedup vs baseline: 1.1205x; 1.1205x over previous
#include <cuda_runtime.h>
#include <cuda_bf16.h>
#include <stdint.h>

#define BB 4096
#define DD 1024
#define RR 256
#define NCTA 128
#define NTHR 512

#define K_W1 1.3512071919596578
#define K_W0 (-1.7024143839193153)
#define K_C1f ((float)(K_W1 * 0.5))
#define K_C2f ((float)((K_W0 + K_W1) * 0.5))
#define K_DT 0.01f

// -------- device-global scratch (no runtime allocation) --------
__device__ __align__(1024) unsigned char g_Ub[16 * 32768];   // U bf16: 16 k-chunks [256n x 64k] SW128
__device__ __align__(1024) unsigned char g_Wb[64 * 8192];    // W bf16: 16 n-chunks x 4 k-tiles [64n x 64k] SW128
__device__ __align__(1024) float g_vf[(size_t)BB * DD];      // v fp32 master

// -------- helpers --------
__device__ __forceinline__ uint32_t swz(uint32_t o) { return o ^ ((o >> 3) & 0x70); }
__device__ __forceinline__ uint32_t s2u(const void* p) {
    uint32_t a; asm("{ .reg .u64 t; cvta.to.shared.u64 t, %1; cvt.u32.u64 %0, t; }" : "=r"(a) : "l"(p)); return a;
}
__device__ __forceinline__ uint32_t bf2u(__nv_bfloat162 b) { return *reinterpret_cast<uint32_t*>(&b); }
__device__ __forceinline__ void mb_init(uint32_t a, uint32_t c) {
    asm volatile("mbarrier.init.shared.b64 [%0], %1;" :: "r"(a), "r"(c) : "memory");
}
__device__ __forceinline__ void mb_expect(uint32_t a, uint32_t b) {
    asm volatile("mbarrier.arrive.expect_tx.shared.b64 _, [%0], %1;" :: "r"(a), "r"(b) : "memory");
}
__device__ __forceinline__ void mb_wait(uint32_t a, uint32_t p) {
    asm volatile("{\n\t.reg .pred P;\n\tLW%=:\n\t"
        "mbarrier.try_wait.parity.acquire.cta.shared::cta.b64 P, [%0], %1, 0x989680;\n\t"
        "@P bra LD%=;\n\tbra LW%=;\n\tLD%=:\n\t}" :: "r"(a), "r"(p) : "memory");
}
__device__ __forceinline__ void bulkcp(uint32_t d, const void* s, uint32_t n, uint32_t mb) {
    asm volatile("cp.async.bulk.shared::cluster.global.mbarrier::complete_tx::bytes [%0], [%1], %2, [%3];"
                 :: "r"(d), "l"(s), "r"(n), "r"(mb) : "memory");
}
__device__ __forceinline__ void fence_async_sh() { asm volatile("fence.proxy.async.shared::cta;" ::: "memory"); }
__device__ __forceinline__ void ldsm4(uint32_t* r, uint32_t a) {
    asm volatile("ldmatrix.sync.aligned.m8n8.x4.shared.b16 {%0,%1,%2,%3}, [%4];"
                 : "=r"(r[0]), "=r"(r[1]), "=r"(r[2]), "=r"(r[3]) : "r"(a));
}
__device__ __forceinline__ void ldsm2(uint32_t* r, uint32_t a) {
    asm volatile("ldmatrix.sync.aligned.m8n8.x2.shared.b16 {%0,%1}, [%2];"
                 : "=r"(r[0]), "=r"(r[1]) : "r"(a));
}
__device__ __forceinline__ void mma16816(float* c, const uint32_t* a, const uint32_t* b) {
    asm volatile("mma.sync.aligned.m16n8k16.row.col.f32.bf16.bf16.f32 "
        "{%0,%1,%2,%3}, {%4,%5,%6,%7}, {%8,%9}, {%0,%1,%2,%3};"
        : "+f"(c[0]), "+f"(c[1]), "+f"(c[2]), "+f"(c[3])
        : "r"(a[0]), "r"(a[1]), "r"(a[2]), "r"(a[3]), "r"(b[0]), "r"(b[1]));
}
__device__ __forceinline__ void sts32(uint32_t a, uint32_t v) {
    asm volatile("st.shared.b32 [%0], %1;" :: "r"(a), "r"(v) : "memory");
}
__device__ __forceinline__ void sts64(uint32_t a, uint32_t v0, uint32_t v1) {
    asm volatile("st.shared.v2.u32 [%0], {%1, %2};" :: "r"(a), "r"(v0), "r"(v1) : "memory");
}
__device__ __forceinline__ const unsigned char* chunk_src(int g) {
    int l = g & 31;
    return (l < 16) ? (g_Ub + (size_t)l * 32768) : (g_Wb + (size_t)(l - 16) * 32768);
}

// -------- prologue: fp32 -> bf16 SW128 tiles in gmem --------
__global__ void prep_uw_kernel(const float* __restrict__ U, const float* __restrict__ W) {
    int idx = blockIdx.x * blockDim.x + threadIdx.x;       // 262144
    if (idx < 131072) {                                    // U: kc(16) x r(256) x j(32 pairs)
        int kc = idx >> 13, rem = idx & 8191, r = rem >> 5, j = rem & 31;
        float2 f = *(const float2*)(U + (size_t)r * DD + kc * 64 + j * 2);
        *(uint32_t*)(g_Ub + kc * 32768 + swz((uint32_t)(r * 128 + j * 4))) = bf2u(__float22bfloat162_rn(f));
    } else {                                               // W: 64 tiles (nc*4+kt) x dr(64) x j(32)
        int i2 = idx - 131072;
        int t = i2 >> 11, rem = i2 & 2047, dr = rem >> 5, j = rem & 31;
        int nc = t >> 2, kt = t & 3;
        float2 f = *(const float2*)(W + (size_t)(nc * 64 + dr) * RR + kt * 64 + j * 2);
        *(uint32_t*)(g_Wb + t * 8192 + swz((uint32_t)(dr * 128 + j * 4))) = bf2u(__float22bfloat162_rn(f));
    }
}

// -------- fused elementwise for one 64-d chunk (one float4 per thread) --------
__device__ __forceinline__ void ew_chunk(
    int c, const float* SGb, int step, float dcoef,
    const float* __restrict__ x, const float* __restrict__ vsrc,
    const float* __restrict__ force, float* __restrict__ out,
    uint32_t SV, int er, int el, size_t grow)
{
    const int d = c * 64 + el;
    float4 g4 = *(const float4*)(SGb + er * 68 + el);
    float4 f4 = *(const float4*)(force + grow + d);
    float4 v4 = *(const float4*)(vsrc + grow + d);
    float4 vn;
    vn.x = v4.x + dcoef * (f4.x - g4.x);
    vn.y = v4.y + dcoef * (f4.y - g4.y);
    vn.z = v4.z + dcoef * (f4.z - g4.z);
    vn.w = v4.w + dcoef * (f4.w - g4.w);
    *(float4*)(g_vf + grow + d) = vn;
    sts64(SV + (uint32_t)c * 4096u + swz((uint32_t)(er * 128 + el * 2)),
          bf2u(__float22bfloat162_rn(make_float2(vn.x, vn.y))),
          bf2u(__float22bfloat162_rn(make_float2(vn.z, vn.w))));
    float4* ox = (float4*)(out + grow + d);
    if (step == 0) {
        float4 t;
        t.x = K_C1f * v4.x + K_C2f * vn.x; t.y = K_C1f * v4.y + K_C2f * vn.y;
        t.z = K_C1f * v4.z + K_C2f * vn.z; t.w = K_C1f * v4.w + K_C2f * vn.w;
        *ox = t;
    } else if (step == 1) {
        float4 t = *ox;
        t.x += K_C2f * vn.x; t.y += K_C2f * vn.y;
        t.z += K_C2f * vn.z; t.w += K_C2f * vn.w;
        *ox = t;
    } else {
        float4 t = *ox;
        float4 x4 = *(const float4*)(x + grow + d);
        t.x = x4.x + K_DT * (t.x + K_C1f * vn.x);
        t.y = x4.y + K_DT * (t.y + K_C1f * vn.y);
        t.z = x4.z + K_DT * (t.z + K_C1f * vn.z);
        t.w = x4.w + K_DT * (t.w + K_C1f * vn.w);
        *ox = t;
        *(float4*)(out + (size_t)BB * DD + grow + d) = vn;
    }
}

// -------- main fused integrator (16 warps) --------
__global__ __launch_bounds__(NTHR, 1)
void yoshida_mma3_kernel(const float* __restrict__ x, const float* __restrict__ v,
                         const float* __restrict__ force, float* __restrict__ out) {
    extern __shared__ unsigned char dsm[];
    unsigned char* basep = (unsigned char*)(((uintptr_t)dsm + 1023u) & ~(uintptr_t)1023u);
    const uint32_t base = s2u(basep);
    const uint32_t SV   = base;                 // 64KB resident v bf16: 16 tiles [32 x 64] SW128
    const uint32_t RING = base + 65536u;        // 4 x 32KB unified U/W chunk ring
    const uint32_t H2   = base + 196608u;       // 4 x 4KB h^2 tiles [32 x 64] bf16 SW128
    float* SG0 = (float*)(basep + 212992u);     // sGamma ping [32][68] f32
    float* SG1 = (float*)(basep + 212992u + 8704u);
    const uint32_t BARS = base + 230400u;

    const int tid = threadIdx.x, wid = tid >> 5, lid = tid & 31;
    const int mh = wid >> 3;                   // M half: rows mh*16..+15
    const int q  = wid & 7;                    // N octant
    const int row0 = blockIdx.x * 32;

    const uint32_t arow  = (uint32_t)((mh * 16 + (lid & 15)) * 128 + ((lid >> 4) << 4));
    const uint32_t brow  = (uint32_t)(((lid & 7) + ((lid >> 4) << 3)) * 128 + (((lid >> 3) & 1) << 4));
    const uint32_t brow2 = (uint32_t)((lid & 7) * 128 + (((lid >> 3) & 1) << 4));
    const int hr = lid >> 2, hc2 = (lid & 3) * 2;
    const int er = tid >> 4, el = (tid & 15) * 4;
    const size_t grow = (size_t)(row0 + er) * DD;

    if (tid == 0) {
        #pragma unroll
        for (int i = 0; i < 4; ++i) mb_init(BARS + 8u * i, 1);
        fence_async_sh();
        #pragma unroll
        for (int c = 0; c < 4; ++c) {
            mb_expect(BARS + 8u * c, 32768u);
            bulkcp(RING + (uint32_t)c * 32768u, chunk_src(c), 32768u, BARS + 8u * c);
        }
    }

    // resident sV init: bf16(v) pre-swizzled
    for (int i = tid; i < 8192; i += NTHR) {
        int row = i >> 8, rem = i & 255, kc = rem >> 4, jj = rem & 15;
        float4 f = *(const float4*)(v + (size_t)(row0 + row) * DD + kc * 64 + jj * 4);
        sts64(SV + (uint32_t)kc * 4096u + swz((uint32_t)(row * 128 + jj * 8)),
              bf2u(__float22bfloat162_rn(make_float2(f.x, f.y))),
              bf2u(__float22bfloat162_rn(make_float2(f.z, f.w))));
    }
    __syncthreads();

    const float dctab[3] = { (float)K_W1 * K_DT, (float)K_W0 * K_DT, (float)K_W1 * K_DT };

    for (int step = 0; step < 3; ++step) {
        const float dcoef = dctab[step];
        const float* vsrc = (step == 0) ? v : g_vf;

        // ===== GEMM1: h[32 x 256] = sV @ U^T, K=1024 in 16 ring chunks =====
        float acc1[4][4];
        #pragma unroll
        for (int t = 0; t < 4; ++t)
            #pragma unroll
            for (int j = 0; j < 4; ++j) acc1[t][j] = 0.f;

        for (int kc = 0; kc < 16; ++kc) {
            const int b = kc & 3;
            mb_wait(BARS + 8u * b, (uint32_t)((kc >> 2) & 1));
            const uint32_t Ab = SV + (uint32_t)kc * 4096u;
            const uint32_t Bb = RING + (uint32_t)b * 32768u;
            #pragma unroll
            for (int ks = 0; ks < 4; ++ks) {
                uint32_t a[4];
                ldsm4(a, Ab + swz(arow + ks * 32));
                #pragma unroll
                for (int ntp = 0; ntp < 2; ++ntp) {
                    uint32_t bb[4];
                    ldsm4(bb, Bb + swz(brow + (uint32_t)((q * 32 + ntp * 16) * 128) + ks * 32));
                    mma16816(acc1[2 * ntp],     a, bb);
                    mma16816(acc1[2 * ntp + 1], a, bb + 2);
                }
            }
            __syncthreads();
            const int g = step * 32 + kc;
            if (tid == 0 && g + 4 < 96) {
                mb_expect(BARS + 8u * b, 32768u);
                bulkcp(RING + (uint32_t)b * 32768u, chunk_src(g + 4), 32768u, BARS + 8u * b);
            }
        }

        // ---- h^2 -> bf16 SW128 H2 tiles ----
        {
            const uint32_t ht = H2 + (uint32_t)(q >> 1) * 4096u;
            #pragma unroll
            for (int t = 0; t < 4; ++t) {
                const int ntp = t >> 1, half = t & 1;
                float c0 = acc1[t][0], c1 = acc1[t][1], c2 = acc1[t][2], c3 = acc1[t][3];
                uint32_t p0 = bf2u(__float22bfloat162_rn(make_float2(c0 * c0, c1 * c1)));
                uint32_t p1 = bf2u(__float22bfloat162_rn(make_float2(c2 * c2, c3 * c3)));
                uint32_t koff = (uint32_t)(((q & 1) * 32 + ntp * 16 + half * 8 + hc2) * 2);
                sts32(ht + swz((uint32_t)((mh * 16 + hr) * 128) + koff), p0);
                sts32(ht + swz((uint32_t)((mh * 16 + hr + 8) * 128) + koff), p1);
            }
        }
        __syncthreads();

        // ===== GEMM2: Gamma = h2 @ W^T, 16 n-chunks of 64, software-pipelined =====
        float acc2[2][4];
        for (int it = 0; it <= 16; ++it) {
            if (it < 16) {
                const int b = it & 3;
                mb_wait(BARS + 8u * b, (uint32_t)((it >> 2) & 1));
                const int cur = it & 1;
                #pragma unroll
                for (int j = 0; j < 4; ++j) acc2[cur][j] = 0.f;
                const uint32_t Bc = RING + (uint32_t)b * 32768u + (uint32_t)q * 1024u;
                #pragma unroll
                for (int kt = 0; kt < 4; ++kt) {
                    const uint32_t At = H2 + (uint32_t)kt * 4096u;
                    const uint32_t Bt = Bc + (uint32_t)kt * 8192u;
                    #pragma unroll
                    for (int ks = 0; ks < 4; ++ks) {
                        uint32_t a[4], b2[2];
                        ldsm4(a,  At + swz(arow + ks * 32));
                        ldsm2(b2, Bt + swz(brow2 + ks * 32));
                        mma16816(acc2[cur], a, b2);
                    }
                }
            }
            if (it > 0) {   // SG store for previous chunk (pong accumulators)
                const int c = it - 1, pb = c & 1;
                float* SGb = pb ? SG1 : SG0;
                const float* A = acc2[pb];
                const int rbase = (mh * 16 + hr) * 68 + q * 8 + hc2;
                *(float2*)(SGb + rbase)          = make_float2(A[0], A[1]);
                *(float2*)(SGb + rbase + 8 * 68) = make_float2(A[2], A[3]);
            }
            __syncthreads();
            if (it < 16 && tid == 0) {
                const int g = step * 32 + 16 + it;
                if (g + 4 < 96) {
                    const int b = it & 3;
                    mb_expect(BARS + 8u * b, 32768u);
                    bulkcp(RING + (uint32_t)b * 32768u, chunk_src(g + 4), 32768u, BARS + 8u * b);
                }
            }
            if (it > 0) {   // elementwise for previous chunk (overlaps MMA of current)
                const int c = it - 1;
                ew_chunk(c, (c & 1) ? SG1 : SG0, step, dcoef, x, vsrc, force, out,
                         SV, er, el, grow);
            }
        }
    }
}

extern "C" void kernel_launch(void* const* d_in, const int* in_sizes, int n_in,
                              void* d_out, int out_size)
{
    const float* x     = (const float*)d_in[0];
    const float* v     = (const float*)d_in[1];
    const float* force = (const float*)d_in[2];
    const float* U     = (const float*)d_in[3];
    const float* W     = (const float*)d_in[4];
    float* out = (float*)d_out;

    const int smem_bytes = 231456;
    cudaFuncSetAttribute(yoshida_mma3_kernel, cudaFuncAttributeMaxDynamicSharedMemorySize, smem_bytes);

    prep_uw_kernel<<<1024, 256>>>(U, W);
    yoshida_mma3_kernel<<<NCTA, NTHR, smem_bytes>>>(x, v, force, out);
}